// round 10
// baseline (speedup 1.0000x reference)
#include <cuda_runtime.h>
#include <cuda_fp16.h>
#include <math.h>
#include <stdint.h>

// ---------------- problem constants ----------------
#define BB 4
#define NN 1024
#define DDIM 1024
#define HH 16
#define CTXN 77
#define CTXD 768
#define FFIN 8192
#define FFHID 4096
#define TOK (BB*NN)      // 4096
#define CTOK (BB*CTXN)   // 308
#define SCALE 0.125f
#define RSC 2048.0f
#define RSCINV (1.0f/2048.0f)
#define QKVSTRIDE ((size_t)TOK*DDIM)

// ---------------- scratch (device globals) ----------------
__device__ char  g_qkv8[(size_t)3*TOK*DDIM];     // q8 | k8 | v8, each [b,h,n,64]
__device__ unsigned char g_w8[(size_t)BB*HH*NN*NN];
__device__ float g_sim[(size_t)BB*HH*NN*NN];     // scores; reused for FF hidden

#define AMAX ((size_t)TOK*FFHID)
__device__ __half g_ah[AMAX];
__device__ __half g_am[AMAX];

#define OFF_WQ1  ((size_t)0)
#define OFF_WK1  ((size_t)1048576)
#define OFF_WV1  ((size_t)2097152)
#define OFF_WO1  ((size_t)3145728)
#define OFF_WQ2  ((size_t)4194304)
#define OFF_WO2  ((size_t)5242880)
#define OFF_WK2  ((size_t)6291456)
#define OFF_WV2  ((size_t)(6291456+786432))
#define OFF_FF1  ((size_t)(6291456+1572864))
#define OFF_FF2  ((size_t)(OFF_FF1+8388608))
#define WTOT     ((size_t)(OFF_FF2+4194304))
__device__ __half g_wh[WTOT];
__device__ __half g_wm[WTOT];

// ---------------- helpers ----------------
__device__ __forceinline__ uint32_t smem_u32(const void* p) {
    uint32_t a;
    asm("{ .reg .u64 t; cvta.to.shared.u64 t, %1; cvt.u32.u64 %0, t; }" : "=r"(a) : "l"(p));
    return a;
}
__device__ __forceinline__ void cpasync16(uint32_t s, const void* g, int sz) {
    asm volatile("cp.async.cg.shared.global [%0], [%1], 16, %2;"
                 :: "r"(s), "l"(g), "r"(sz));
}
__device__ __forceinline__ void cpcommit() { asm volatile("cp.async.commit_group;"); }
__device__ __forceinline__ void cpwait2()  { asm volatile("cp.async.wait_group 2;"); }

__device__ __forceinline__ void split2(float x, __half& h, __half& m) {
    h = __float2half_rn(x);
    m = __float2half_rn((x - __half2float(h)) * RSC);
}

// ---------------- LayerNorm -> (h,m) planes ----------------
__global__ void __launch_bounds__(256) ln_kernel(const float* __restrict__ x,
    const float* __restrict__ w, const float* __restrict__ b,
    __half* __restrict__ H, __half* __restrict__ Mp)
{
    int row = blockIdx.x;
    int t = threadIdx.x;
    const float4* xr = (const float4*)(x + (size_t)row * DDIM);
    float4 v = xr[t];
    float s  = v.x + v.y + v.z + v.w;
    float ss = v.x*v.x + v.y*v.y + v.z*v.z + v.w*v.w;
    #pragma unroll
    for (int o = 16; o; o >>= 1) {
        s  += __shfl_xor_sync(0xffffffffu, s, o);
        ss += __shfl_xor_sync(0xffffffffu, ss, o);
    }
    __shared__ float sh_s[8], sh_q[8];
    int wid = t >> 5, lane = t & 31;
    if (lane == 0) { sh_s[wid] = s; sh_q[wid] = ss; }
    __syncthreads();
    if (t == 0) {
        float a = 0.f, c = 0.f;
        #pragma unroll
        for (int i = 0; i < 8; i++) { a += sh_s[i]; c += sh_q[i]; }
        float m = a * (1.0f/DDIM);
        float var = c * (1.0f/DDIM) - m*m;
        sh_s[0] = m;
        sh_q[0] = rsqrtf(var + 1e-5f);
    }
    __syncthreads();
    float m = sh_s[0], r = sh_q[0];
    float4 wv = ((const float4*)w)[t];
    float4 bv = ((const float4*)b)[t];
    float o[4];
    o[0] = (v.x - m) * r * wv.x + bv.x;
    o[1] = (v.y - m) * r * wv.y + bv.y;
    o[2] = (v.z - m) * r * wv.z + bv.z;
    o[3] = (v.w - m) * r * wv.w + bv.w;
    ushort4 uh, um;
    __half h0, m0;
    split2(o[0], h0, m0); uh.x = __half_as_ushort(h0); um.x = __half_as_ushort(m0);
    split2(o[1], h0, m0); uh.y = __half_as_ushort(h0); um.y = __half_as_ushort(m0);
    split2(o[2], h0, m0); uh.z = __half_as_ushort(h0); um.z = __half_as_ushort(m0);
    split2(o[3], h0, m0); uh.w = __half_as_ushort(h0); um.w = __half_as_ushort(m0);
    ((ushort4*)(H  + (size_t)row * DDIM))[t] = uh;
    ((ushort4*)(Mp + (size_t)row * DDIM))[t] = um;
}

// ---------------- activation split (ctx only) ----------------
__global__ void __launch_bounds__(256) asplit_k(const float* __restrict__ A,
    __half* __restrict__ H, __half* __restrict__ Mp, int n4)
{
    int i = blockIdx.x * 256 + threadIdx.x;
    if (i >= n4) return;
    float4 v = ((const float4*)A)[i];
    ushort4 uh, um;
    __half h0, m0;
    split2(v.x, h0, m0); uh.x = __half_as_ushort(h0); um.x = __half_as_ushort(m0);
    split2(v.y, h0, m0); uh.y = __half_as_ushort(h0); um.y = __half_as_ushort(m0);
    split2(v.z, h0, m0); uh.z = __half_as_ushort(h0); um.z = __half_as_ushort(m0);
    split2(v.w, h0, m0); uh.w = __half_as_ushort(h0); um.w = __half_as_ushort(m0);
    ((ushort4*)H)[i] = uh; ((ushort4*)Mp)[i] = um;
}

// ---------------- weight transpose+split (batched) ----------------
struct WS6 { const float* w[6]; };

__device__ __forceinline__ void wsplit_body(const float* __restrict__ W,
    __half* __restrict__ H, __half* __restrict__ Mp, int K, int N)
{
    __shared__ float tile[32][33];
    int n0 = blockIdx.x * 32, k0 = blockIdx.y * 32;
    int tx = threadIdx.x & 31, ty = threadIdx.x >> 5;
    #pragma unroll
    for (int i = 0; i < 4; i++)
        tile[ty + i*8][tx] = W[(size_t)(k0 + ty + i*8) * N + n0 + tx];
    __syncthreads();
    #pragma unroll
    for (int i = 0; i < 4; i++) {
        int nl = ty + i*8;
        float x = tile[tx][nl];
        __half h, m;
        split2(x, h, m);
        size_t o = (size_t)(n0 + nl) * K + k0 + tx;
        H[o] = h; Mp[o] = m;
    }
}

__global__ void __launch_bounds__(256) wsplit6_k(WS6 ws,
    __half* __restrict__ H, __half* __restrict__ Mp)
{
    int z = blockIdx.z;
    size_t off = (size_t)z * 1048576;
    wsplit_body(ws.w[z], H + off, Mp + off, DDIM, DDIM);
}

__global__ void __launch_bounds__(256) wsplit_ctx2_k(const float* __restrict__ wk,
    const float* __restrict__ wv, __half* __restrict__ H, __half* __restrict__ Mp)
{
    int z = blockIdx.z;
    const float* W = z ? wv : wk;
    size_t off = OFF_WK2 + (size_t)z * 786432;
    wsplit_body(W, H + off, Mp + off, CTXD, DDIM);
}

__global__ void __launch_bounds__(256) wsplit1_k(const float* __restrict__ W,
    __half* __restrict__ H, __half* __restrict__ Mp, int K, int N)
{
    wsplit_body(W, H, Mp, K, N);
}

// ---------------- HMMA GEMM: D[M,N] = A[M,K] @ T[N,K]^T, fp16 split --------
// BK=64, 4-stage cp.async pipeline, one barrier/iter, dual accumulators
// (tile acc flushed to fp32 master every 2 iters; RZ chain <= 8 adds).
// TERMS=3: (h,m'), (m',h) [x2048] -> rescale -> (h,h)  (quantizer outputs)
// TERMS=2: (m',h) [x2048] -> rescale -> (h,h)          (smooth outputs)
// MODE 0: fake-quant -> int8, buf = head>>4 demux, per-buf scale (d0/d1/d2)
// MODE 1: +bias+res fp32 ; MODE 2: +bias fp32
#define BM 128
#define BN 128
#define BK 64
#define ROWB 144                  // 128B data + 16B pad
#define ATILE (BM*ROWB)           // 18432
#define STAGEB (2*ATILE)          // 36864
#define NSTAGE 4
#define GSMEM (NSTAGE*STAGEB)     // 147456

template<int MODE, bool BOUNDS, int TERMS>
__global__ void __launch_bounds__(256, 1) hgemm(
    const __half* __restrict__ Ah, const __half* __restrict__ Am,
    const __half* __restrict__ Bh, const __half* __restrict__ Bm,
    const float* __restrict__ bias, const float* __restrict__ res,
    float* __restrict__ Cf, char* __restrict__ Cq,
    int M, int N, int K,
    const float* __restrict__ d0, const float* __restrict__ d1,
    const float* __restrict__ d2, int rows_per_b)
{
    extern __shared__ char smem[];
    const uint32_t sb = smem_u32(smem);
    const int tid  = threadIdx.x;
    const int wid  = tid >> 5;
    const int lane = tid & 31;
    const int m0 = blockIdx.y * BM;
    const int n0 = blockIdx.x * BN;
    const int wrow = (wid >> 2) * 64;
    const int wcol = (wid & 3) * 32;

    const int KT = K >> 6;          // 64-wide K tiles
    const int T = TERMS * KT;       // even for all our shapes

    const __half* APL[3];
    const __half* BPL[3];
    if (TERMS == 3) {
        APL[0]=Ah; BPL[0]=Bm;
        APL[1]=Am; BPL[1]=Bh;
        APL[2]=Ah; BPL[2]=Bh;
    } else {
        APL[0]=Am; BPL[0]=Bh;
        APL[1]=Ah; BPL[1]=Bh;
        APL[2]=Ah; BPL[2]=Bh;
    }

    int lkt = 0, lterm = 0;
    const __half* lpa = APL[0];
    const __half* lpb = BPL[0];

    const int arow = tid >> 1;         // 0..127
    const int aco  = (tid & 1) * 64;   // 0 or 64 bytes
    int grow = m0 + arow;
    if (BOUNDS && grow >= M) grow = M - 1;
    const int asz = (!BOUNDS || (m0 + arow) < M) ? 16 : 0;

    auto issue = [&](int buf) {
        const char* ga = (const char*)lpa + (((size_t)grow*K + lkt*BK) << 1) + aco;
        uint32_t sa = sb + buf*STAGEB + arow*ROWB + aco;
        cpasync16(sa,      ga,      asz);
        cpasync16(sa + 16, ga + 16, asz);
        cpasync16(sa + 32, ga + 32, asz);
        cpasync16(sa + 48, ga + 48, asz);
        const char* gb = (const char*)lpb + (((size_t)(n0+arow)*K + lkt*BK) << 1) + aco;
        uint32_t sbb = sb + buf*STAGEB + ATILE + arow*ROWB + aco;
        cpasync16(sbb,      gb,      16);
        cpasync16(sbb + 16, gb + 16, 16);
        cpasync16(sbb + 32, gb + 32, 16);
        cpasync16(sbb + 48, gb + 48, 16);
    };
    auto adv = [&]() {
        if (++lkt == KT) {
            lkt = 0;
            ++lterm;
            int tt = lterm < TERMS ? lterm : TERMS-1;
            lpa = APL[tt];
            lpb = BPL[tt];
        }
    };

    float acc[4][4][4];
    float accm[4][4][4];
    #pragma unroll
    for (int i = 0; i < 4; i++)
        #pragma unroll
        for (int j = 0; j < 4; j++)
            #pragma unroll
            for (int r = 0; r < 4; r++) { acc[i][j][r] = 0.f; accm[i][j][r] = 0.f; }

    issue(0); adv(); cpcommit();
    issue(1); adv(); cpcommit();

    const int rescIt = (TERMS == 3) ? 2*KT : KT;   // even; acc flushed at odd its

    for (int it = 0; it < T; it++) {
        if (it + 2 < T) { issue((it + 2) % NSTAGE); adv(); }
        cpcommit();
        cpwait2();
        __syncthreads();
        if (it == rescIt) {
            #pragma unroll
            for (int i = 0; i < 4; i++)
                #pragma unroll
                for (int j = 0; j < 4; j++)
                    #pragma unroll
                    for (int r = 0; r < 4; r++) accm[i][j][r] *= RSCINV;
        }
        const uint32_t abase = sb + (it % NSTAGE) * STAGEB;
        const uint32_t bbase = abase + ATILE;
        #pragma unroll
        for (int kh = 0; kh < 4; kh++) {
            uint32_t b0[4], b1[4];
            #pragma unroll
            for (int nt = 0; nt < 4; nt++) {
                uint32_t ad = bbase + (wcol + nt*8 + (lane & 7))*ROWB
                            + kh*32 + ((lane >> 3) & 1)*16;
                asm volatile("ldmatrix.sync.aligned.m8n8.x2.shared.b16 {%0,%1}, [%2];"
                             : "=r"(b0[nt]), "=r"(b1[nt]) : "r"(ad));
            }
            #pragma unroll
            for (int mt = 0; mt < 4; mt++) {
                uint32_t a0, a1, a2, a3;
                uint32_t ad = abase + (wrow + mt*16 + ((lane >> 3) & 1)*8 + (lane & 7))*ROWB
                            + kh*32 + ((lane >> 4) & 1)*16;
                asm volatile("ldmatrix.sync.aligned.m8n8.x4.shared.b16 {%0,%1,%2,%3}, [%4];"
                             : "=r"(a0), "=r"(a1), "=r"(a2), "=r"(a3) : "r"(ad));
                #pragma unroll
                for (int nt = 0; nt < 4; nt++) {
                    asm volatile(
                        "mma.sync.aligned.m16n8k16.row.col.f32.f16.f16.f32 "
                        "{%0,%1,%2,%3}, {%4,%5,%6,%7}, {%8,%9}, {%0,%1,%2,%3};"
                        : "+f"(acc[mt][nt][0]), "+f"(acc[mt][nt][1]),
                          "+f"(acc[mt][nt][2]), "+f"(acc[mt][nt][3])
                        : "r"(a0), "r"(a1), "r"(a2), "r"(a3), "r"(b0[nt]), "r"(b1[nt]));
                }
            }
        }
        if (it & 1) {
            #pragma unroll
            for (int i = 0; i < 4; i++)
                #pragma unroll
                for (int j = 0; j < 4; j++)
                    #pragma unroll
                    for (int r = 0; r < 4; r++) {
                        accm[i][j][r] += acc[i][j][r];
                        acc[i][j][r] = 0.f;
                    }
        }
    }

    // ---------------- epilogue ----------------
    float d = 0.f, invd = 0.f;
    if (MODE == 0) {
        int bsel = n0 >> 10;   // constant per CTA (128-wide tile never crosses 1024)
        const float* dp = (bsel == 0) ? d0 : ((bsel == 1) ? d1 : d2);
        d = *dp; invd = 1.0f / d;
    }
    #pragma unroll
    for (int mt = 0; mt < 4; mt++) {
        int r0 = m0 + wrow + mt*16 + (lane >> 2);
        #pragma unroll
        for (int nt = 0; nt < 4; nt++) {
            int nc = n0 + wcol + nt*8 + (lane & 3)*2;
            #pragma unroll
            for (int hrow = 0; hrow < 2; hrow++) {
                int rr = r0 + hrow*8;
                if (BOUNDS && rr >= M) continue;
                float c0 = accm[mt][nt][hrow*2+0];
                float c1 = accm[mt][nt][hrow*2+1];
                if (MODE == 0) {
                    int hg = nc >> 6;
                    int buf = hg >> 4;
                    int hl  = hg & 15;
                    int dd  = nc & 63;
                    int b = rr / rows_per_b;
                    int n = rr - b * rows_per_b;
                    char2 pk;
                    pk.x = (char)(int)fminf(fmaxf(rintf(c0 * invd), -128.f), 127.f);
                    pk.y = (char)(int)fminf(fmaxf(rintf(c1 * invd), -128.f), 127.f);
                    *(char2*)(Cq + (size_t)buf*QKVSTRIDE
                              + ((size_t)(b*HH + hl)*rows_per_b + n)*64 + dd) = pk;
                } else {
                    size_t off = (size_t)rr * N + nc;
                    float2 o;
                    o.x = c0 + bias[nc];
                    o.y = c1 + bias[nc+1];
                    if (MODE == 1) {
                        float2 rv = *(const float2*)(res + off);
                        o.x += rv.x; o.y += rv.y;
                    }
                    *(float2*)(Cf + off) = o;
                }
            }
        }
    }
}

// ---------------- int8 scores ----------------
__global__ void __launch_bounds__(256) sim8_kernel(
    const char* __restrict__ Q8, const char* __restrict__ K8,
    float* __restrict__ S, int nk,
    const float* __restrict__ dq, const float* __restrict__ dk)
{
    int bh = blockIdx.z;
    int i0 = blockIdx.y * 64;
    int j0 = blockIdx.x * 64;
    __shared__ int qs[16][68];
    __shared__ int ks[16][68];
    int tid = threadIdx.x;
    int row = tid >> 2;
    int c4  = (tid & 3) * 4;
    {
        int4 qv = *(const int4*)(Q8 + ((size_t)bh*NN + i0 + row)*64 + c4*4);
        qs[c4+0][row]=qv.x; qs[c4+1][row]=qv.y; qs[c4+2][row]=qv.z; qs[c4+3][row]=qv.w;
        int jr = j0 + row;
        int4 kv = make_int4(0,0,0,0);
        if (jr < nk) kv = *(const int4*)(K8 + ((size_t)bh*nk + jr)*64 + c4*4);
        ks[c4+0][row]=kv.x; ks[c4+1][row]=kv.y; ks[c4+2][row]=kv.z; ks[c4+3][row]=kv.w;
    }
    __syncthreads();
    int ty = tid >> 4, tx = tid & 15;
    int acc[4][4];
    #pragma unroll
    for (int i = 0; i < 4; i++)
        #pragma unroll
        for (int j = 0; j < 4; j++) acc[i][j] = 0;
    #pragma unroll
    for (int kk = 0; kk < 16; kk++) {
        int a[4], b[4];
        *(int4*)a = *(const int4*)&qs[kk][ty*4];
        *(int4*)b = *(const int4*)&ks[kk][tx*4];
        #pragma unroll
        for (int i = 0; i < 4; i++)
            #pragma unroll
            for (int j = 0; j < 4; j++) acc[i][j] = __dp4a(a[i], b[j], acc[i][j]);
    }
    float sc = dq[0] * dk[0] * SCALE;
    #pragma unroll
    for (int i = 0; i < 4; i++) {
        size_t ro = ((size_t)bh*NN + i0 + ty*4 + i) * nk;
        #pragma unroll
        for (int j = 0; j < 4; j++) {
            int jj = j0 + tx*4 + j;
            if (jj < nk) S[ro + jj] = (float)acc[i][j] * sc;
        }
    }
}

// ---------------- softmax + weight quant ----------------
__global__ void __launch_bounds__(128) softmax_quant(
    const float* __restrict__ S, unsigned char* __restrict__ W8,
    int cols, int colsp, const float* __restrict__ dptr)
{
    size_t row = blockIdx.x;
    const float* p = S + row * (size_t)cols;
    unsigned char* o = W8 + row * (size_t)colsp;
    int t = threadIdx.x;
    float buf[8];
    int nb = 0;
    float m = -INFINITY;
    for (int c = t; c < cols; c += 128) {
        float v = p[c];
        buf[nb++] = v;
        m = fmaxf(m, v);
    }
    #pragma unroll
    for (int off = 16; off; off >>= 1) m = fmaxf(m, __shfl_xor_sync(0xffffffffu, m, off));
    __shared__ float redm[4], reds[4];
    if ((t & 31) == 0) redm[t >> 5] = m;
    __syncthreads();
    m = fmaxf(fmaxf(redm[0], redm[1]), fmaxf(redm[2], redm[3]));
    float sum = 0.f;
    for (int i = 0; i < nb; i++) { buf[i] = expf(buf[i] - m); sum += buf[i]; }
    #pragma unroll
    for (int off = 16; off; off >>= 1) sum += __shfl_xor_sync(0xffffffffu, sum, off);
    if ((t & 31) == 0) reds[t >> 5] = sum;
    __syncthreads();
    sum = reds[0] + reds[1] + reds[2] + reds[3];
    float inv = 1.0f / sum;
    float invd = 1.0f / dptr[0];
    nb = 0;
    for (int c = t; c < colsp; c += 128) {
        unsigned char ob = 0;
        if (c < cols) {
            float q = rintf(buf[nb++] * inv * invd);
            ob = (unsigned char)(int)fminf(fmaxf(q, 0.f), 255.f);
        }
        o[c] = ob;
    }
}

// ---------------- AV (u8 x s8 dp4a) -> (h,m) planes ----------------
__global__ void __launch_bounds__(256) av8_kernel(
    const unsigned char* __restrict__ W8, const char* __restrict__ V8,
    __half* __restrict__ OH, __half* __restrict__ OM, int nk, int colsp,
    const float* __restrict__ dw, const float* __restrict__ dv)
{
    int bh = blockIdx.y; int b = bh >> 4; int h = bh & 15;
    int i0 = blockIdx.x * 64;
    __shared__ int ws[64][20];
    __shared__ unsigned char vtb[64][76];
    int tid = threadIdx.x;
    int row = tid >> 2;
    int c16 = (tid & 3) * 16;
    int ty = tid >> 4, tx = tid & 15;
    int acc[4][4];
    #pragma unroll
    for (int i = 0; i < 4; i++)
        #pragma unroll
        for (int d = 0; d < 4; d++) acc[i][d] = 0;

    const unsigned char* wb = W8 + ((size_t)bh*NN + i0 + row) * colsp + c16;
    const char* vb = V8 + ((size_t)bh*nk)*64;

    for (int j0 = 0; j0 < nk; j0 += 64) {
        uint4 wv = *(const uint4*)(wb + j0);
        *(uint4*)&ws[row][(tid & 3) * 4] = wv;
        int jr = j0 + row;
        int4 vv = make_int4(0,0,0,0);
        if (jr < nk) vv = *(const int4*)(vb + (size_t)jr*64 + c16);
        union { int4 v; unsigned char bb[16]; } u; u.v = vv;
        #pragma unroll
        for (int i = 0; i < 16; i++) vtb[c16 + i][row] = u.bb[i];
        __syncthreads();
        #pragma unroll
        for (int kk = 0; kk < 16; kk++) {
            int a[4], bb[4];
            #pragma unroll
            for (int i = 0; i < 4; i++) a[i] = ws[ty*4 + i][kk];
            #pragma unroll
            for (int d = 0; d < 4; d++) bb[d] = *(const int*)&vtb[tx*4 + d][kk*4];
            #pragma unroll
            for (int i = 0; i < 4; i++)
                #pragma unroll
                for (int d = 0; d < 4; d++)
                    asm("dp4a.u32.s32 %0, %1, %2, %3;"
                        : "=r"(acc[i][d]) : "r"(a[i]), "r"(bb[d]), "r"(acc[i][d]));
        }
        __syncthreads();
    }
    float sc = dw[0] * dv[0];
    #pragma unroll
    for (int i = 0; i < 4; i++) {
        size_t ro = ((size_t)(b*NN + i0 + ty*4 + i)) * DDIM + h*64 + tx*4;
        ushort4 uh, um;
        __half hh, mm;
        split2((float)acc[i][0] * sc, hh, mm); uh.x=__half_as_ushort(hh); um.x=__half_as_ushort(mm);
        split2((float)acc[i][1] * sc, hh, mm); uh.y=__half_as_ushort(hh); um.y=__half_as_ushort(mm);
        split2((float)acc[i][2] * sc, hh, mm); uh.z=__half_as_ushort(hh); um.z=__half_as_ushort(mm);
        split2((float)acc[i][3] * sc, hh, mm); uh.w=__half_as_ushort(hh); um.w=__half_as_ushort(mm);
        *(ushort4*)&OH[ro] = uh;
        *(ushort4*)&OM[ro] = um;
    }
}

// ---------------- GEGLU -> (h,m) planes ----------------
__global__ void __launch_bounds__(256) geglu_kernel(const float* __restrict__ h,
    __half* __restrict__ AH, __half* __restrict__ AM)
{
    size_t idx = (size_t)blockIdx.x * blockDim.x + threadIdx.x;
    size_t i  = idx / (FFHID / 4);
    size_t c4 = idx % (FFHID / 4);
    float4 a = *(const float4*)(h + i * FFIN + c4 * 4);
    float4 g = *(const float4*)(h + i * FFIN + FFHID + c4 * 4);
    const float kInvSqrt2 = 0.70710678118654752f;
    float o[4];
    o[0] = a.x * (0.5f * g.x * (1.f + erff(g.x * kInvSqrt2)));
    o[1] = a.y * (0.5f * g.y * (1.f + erff(g.y * kInvSqrt2)));
    o[2] = a.z * (0.5f * g.z * (1.f + erff(g.z * kInvSqrt2)));
    o[3] = a.w * (0.5f * g.w * (1.f + erff(g.w * kInvSqrt2)));
    ushort4 uh, um;
    __half hh, mm;
    split2(o[0], hh, mm); uh.x=__half_as_ushort(hh); um.x=__half_as_ushort(mm);
    split2(o[1], hh, mm); uh.y=__half_as_ushort(hh); um.y=__half_as_ushort(mm);
    split2(o[2], hh, mm); uh.z=__half_as_ushort(hh); um.z=__half_as_ushort(mm);
    split2(o[3], hh, mm); uh.w=__half_as_ushort(hh); um.w=__half_as_ushort(mm);
    ((ushort4*)AH)[idx] = uh;
    ((ushort4*)AM)[idx] = um;
}

// ---------------- launch ----------------
extern "C" void kernel_launch(void* const* d_in, const int* in_sizes, int n_in,
                              void* d_out, int out_size)
{
    const float* x    = (const float*)d_in[0];
    const float* ctx  = (const float*)d_in[1];
    const float* n1w  = (const float*)d_in[2];
    const float* n1b  = (const float*)d_in[3];
    const float* n2w  = (const float*)d_in[4];
    const float* n2b  = (const float*)d_in[5];
    const float* n3w  = (const float*)d_in[6];
    const float* n3b  = (const float*)d_in[7];
    const float* a1wq = (const float*)d_in[8];
    const float* a1wk = (const float*)d_in[9];
    const float* a1wv = (const float*)d_in[10];
    const float* a1wo = (const float*)d_in[11];
    const float* a1bo = (const float*)d_in[12];
    const float* a2wq = (const float*)d_in[13];
    const float* a2wk = (const float*)d_in[14];
    const float* a2wv = (const float*)d_in[15];
    const float* a2wo = (const float*)d_in[16];
    const float* a2bo = (const float*)d_in[17];
    const float* ffw1 = (const float*)d_in[18];
    const float* ffb1 = (const float*)d_in[19];
    const float* ffw2 = (const float*)d_in[20];
    const float* ffb2 = (const float*)d_in[21];
    const float* d1q  = (const float*)d_in[22];
    const float* d1k  = (const float*)d_in[23];
    const float* d1v  = (const float*)d_in[24];
    const float* d1w  = (const float*)d_in[25];
    const float* d2q  = (const float*)d_in[26];
    const float* d2k  = (const float*)d_in[27];
    const float* d2v  = (const float*)d_in[28];
    const float* d2w  = (const float*)d_in[29];
    float* out = (float*)d_out;

    float *sim;
    char *qkv8;
    unsigned char *w8;
    __half *ah, *am, *wh, *wm;
    cudaGetSymbolAddress((void**)&sim,  g_sim);
    cudaGetSymbolAddress((void**)&qkv8, g_qkv8);
    cudaGetSymbolAddress((void**)&w8,   g_w8);
    cudaGetSymbolAddress((void**)&ah,   g_ah);
    cudaGetSymbolAddress((void**)&am,   g_am);
    cudaGetSymbolAddress((void**)&wh,   g_wh);
    cudaGetSymbolAddress((void**)&wm,   g_wm);
    char* q8 = qkv8;
    char* k8 = qkv8 + QKVSTRIDE;
    char* v8 = qkv8 + 2*QKVSTRIDE;
    float* hbuf = sim;

    cudaFuncSetAttribute(hgemm<0,false,3>, cudaFuncAttributeMaxDynamicSharedMemorySize, GSMEM);
    cudaFuncSetAttribute(hgemm<0,true ,3>, cudaFuncAttributeMaxDynamicSharedMemorySize, GSMEM);
    cudaFuncSetAttribute(hgemm<1,false,3>, cudaFuncAttributeMaxDynamicSharedMemorySize, GSMEM);
    cudaFuncSetAttribute(hgemm<1,false,2>, cudaFuncAttributeMaxDynamicSharedMemorySize, GSMEM);
    cudaFuncSetAttribute(hgemm<2,false,2>, cudaFuncAttributeMaxDynamicSharedMemorySize, GSMEM);

    // ---- split all weights (batched; 4 launches) ----
    WS6 ws6;
    ws6.w[0] = a1wq; ws6.w[1] = a1wk; ws6.w[2] = a1wv;
    ws6.w[3] = a1wo; ws6.w[4] = a2wq; ws6.w[5] = a2wo;
    wsplit6_k<<<dim3(DDIM/32, DDIM/32, 6), 256>>>(ws6, wh, wm);
    wsplit_ctx2_k<<<dim3(DDIM/32, CTXD/32, 2), 256>>>(a2wk, a2wv, wh, wm);
    wsplit1_k<<<dim3(FFIN/32, DDIM/32), 256>>>(ffw1, wh+OFF_FF1, wm+OFF_FF1, DDIM, FFIN);
    wsplit1_k<<<dim3(DDIM/32, FFHID/32), 256>>>(ffw2, wh+OFF_FF2, wm+OFF_FF2, FFHID, DDIM);

    // ---- attn1 (self): FUSED qkv GEMM (N=3072, per-buf scales) ----
    ln_kernel<<<TOK, 256>>>(x, n1w, n1b, ah, am);
    hgemm<0,false,3><<<dim3(24,32), 256, GSMEM>>>(ah,am, wh+OFF_WQ1,wm+OFF_WQ1,
        nullptr, nullptr, nullptr, qkv8, TOK, 3072, DDIM, d1q, d1k, d1v, NN);
    sim8_kernel<<<dim3(16,16,BB*HH), 256>>>(q8, k8, sim, NN, d1q, d1k);
    softmax_quant<<<BB*HH*NN, 128>>>(sim, w8, NN, NN, d1w);
    av8_kernel<<<dim3(16,BB*HH), 256>>>(w8, v8, ah, am, NN, NN, d1w, d1v);
    hgemm<1,false,3><<<dim3(8,32), 256, GSMEM>>>(ah,am, wh+OFF_WO1,wm+OFF_WO1,
        a1bo, x, out, nullptr, TOK, DDIM, DDIM, nullptr, nullptr, nullptr, 0);

    // ---- attn2 (cross): q2 alone; k2+v2 FUSED (N=2048) ----
    ln_kernel<<<TOK, 256>>>(out, n2w, n2b, ah, am);
    hgemm<0,false,3><<<dim3(8,32), 256, GSMEM>>>(ah,am, wh+OFF_WQ2,wm+OFF_WQ2,
        nullptr, nullptr, nullptr, q8, TOK, DDIM, DDIM, d2q, d2q, d2q, NN);
    asplit_k<<<(CTOK*CTXD/4 + 255)/256, 256>>>(ctx, ah, am, CTOK*CTXD/4);
    hgemm<0,true ,3><<<dim3(16,3), 256, GSMEM>>>(ah,am, wh+OFF_WK2,wm+OFF_WK2,
        nullptr, nullptr, nullptr, k8, CTOK, 2048, CTXD, d2k, d2v, d2v, CTXN);
    sim8_kernel<<<dim3(2,16,BB*HH), 256>>>(q8, k8, sim, CTXN, d2q, d2k);
    softmax_quant<<<BB*HH*NN, 128>>>(sim, w8, CTXN, 128, d2w);
    av8_kernel<<<dim3(16,BB*HH), 256>>>(w8, v8, ah, am, CTXN, 128, d2w, d2v);
    hgemm<1,false,2><<<dim3(8,32), 256, GSMEM>>>(ah,am, wh+OFF_WO2,wm+OFF_WO2,
        a2bo, out, out, nullptr, TOK, DDIM, DDIM, nullptr, nullptr, nullptr, 0);

    // ---- GEGLU FF ----
    ln_kernel<<<TOK, 256>>>(out, n3w, n3b, ah, am);
    hgemm<2,false,2><<<dim3(64,32), 256, GSMEM>>>(ah,am, wh+OFF_FF1,wm+OFF_FF1,
        ffb1, nullptr, hbuf, nullptr, TOK, FFIN, DDIM, nullptr, nullptr, nullptr, 0);
    geglu_kernel<<<(TOK*(FFHID/4))/256, 256>>>(hbuf, ah, am);
    hgemm<1,false,2><<<dim3(8,32), 256, GSMEM>>>(ah,am, wh+OFF_FF2,wm+OFF_FF2,
        ffb2, out, out, nullptr, TOK, DDIM, FFHID, nullptr, nullptr, nullptr, 0);
}

// round 11
// speedup vs baseline: 1.0412x; 1.0412x over previous
#include <cuda_runtime.h>
#include <cuda_fp16.h>
#include <math.h>
#include <stdint.h>

// ---------------- problem constants ----------------
#define BB 4
#define NN 1024
#define DDIM 1024
#define HH 16
#define CTXN 77
#define CTXD 768
#define FFIN 8192
#define FFHID 4096
#define TOK (BB*NN)      // 4096
#define CTOK (BB*CTXN)   // 308
#define SCALE 0.125f
#define RSC 2048.0f
#define RSCINV (1.0f/2048.0f)
#define QKVSTRIDE ((size_t)TOK*DDIM)

// ---------------- scratch (device globals) ----------------
__device__ char  g_qkv8[(size_t)3*TOK*DDIM];     // q8 | k8 | v8, each [b,h,n,64]
__device__ unsigned char g_w8[(size_t)BB*HH*NN*NN];
__device__ float g_sim[(size_t)BB*HH*NN*NN];     // scores; reused for FF hidden

#define AMAX ((size_t)TOK*FFHID)
__device__ __half g_ah[AMAX];
__device__ __half g_am[AMAX];

#define OFF_WQ1  ((size_t)0)
#define OFF_WK1  ((size_t)1048576)
#define OFF_WV1  ((size_t)2097152)
#define OFF_WO1  ((size_t)3145728)
#define OFF_WQ2  ((size_t)4194304)
#define OFF_WO2  ((size_t)5242880)
#define OFF_WK2  ((size_t)6291456)
#define OFF_WV2  ((size_t)(6291456+786432))
#define OFF_FF1  ((size_t)(6291456+1572864))
#define OFF_FF2  ((size_t)(OFF_FF1+8388608))
#define WTOT     ((size_t)(OFF_FF2+4194304))
__device__ __half g_wh[WTOT];
__device__ __half g_wm[WTOT];

// ---------------- helpers ----------------
__device__ __forceinline__ uint32_t smem_u32(const void* p) {
    uint32_t a;
    asm("{ .reg .u64 t; cvta.to.shared.u64 t, %1; cvt.u32.u64 %0, t; }" : "=r"(a) : "l"(p));
    return a;
}
__device__ __forceinline__ void cpasync16(uint32_t s, const void* g, int sz) {
    asm volatile("cp.async.cg.shared.global [%0], [%1], 16, %2;"
                 :: "r"(s), "l"(g), "r"(sz));
}
__device__ __forceinline__ void cpcommit() { asm volatile("cp.async.commit_group;"); }
__device__ __forceinline__ void cpwait2()  { asm volatile("cp.async.wait_group 2;"); }

__device__ __forceinline__ void split2(float x, __half& h, __half& m) {
    h = __float2half_rn(x);
    m = __float2half_rn((x - __half2float(h)) * RSC);
}

// ---------------- LayerNorm -> (h,m) planes ----------------
__global__ void __launch_bounds__(256) ln_kernel(const float* __restrict__ x,
    const float* __restrict__ w, const float* __restrict__ b,
    __half* __restrict__ H, __half* __restrict__ Mp)
{
    int row = blockIdx.x;
    int t = threadIdx.x;
    const float4* xr = (const float4*)(x + (size_t)row * DDIM);
    float4 v = xr[t];
    float s  = v.x + v.y + v.z + v.w;
    float ss = v.x*v.x + v.y*v.y + v.z*v.z + v.w*v.w;
    #pragma unroll
    for (int o = 16; o; o >>= 1) {
        s  += __shfl_xor_sync(0xffffffffu, s, o);
        ss += __shfl_xor_sync(0xffffffffu, ss, o);
    }
    __shared__ float sh_s[8], sh_q[8];
    int wid = t >> 5, lane = t & 31;
    if (lane == 0) { sh_s[wid] = s; sh_q[wid] = ss; }
    __syncthreads();
    if (t == 0) {
        float a = 0.f, c = 0.f;
        #pragma unroll
        for (int i = 0; i < 8; i++) { a += sh_s[i]; c += sh_q[i]; }
        float m = a * (1.0f/DDIM);
        float var = c * (1.0f/DDIM) - m*m;
        sh_s[0] = m;
        sh_q[0] = rsqrtf(var + 1e-5f);
    }
    __syncthreads();
    float m = sh_s[0], r = sh_q[0];
    float4 wv = ((const float4*)w)[t];
    float4 bv = ((const float4*)b)[t];
    float o[4];
    o[0] = (v.x - m) * r * wv.x + bv.x;
    o[1] = (v.y - m) * r * wv.y + bv.y;
    o[2] = (v.z - m) * r * wv.z + bv.z;
    o[3] = (v.w - m) * r * wv.w + bv.w;
    ushort4 uh, um;
    __half h0, m0;
    split2(o[0], h0, m0); uh.x = __half_as_ushort(h0); um.x = __half_as_ushort(m0);
    split2(o[1], h0, m0); uh.y = __half_as_ushort(h0); um.y = __half_as_ushort(m0);
    split2(o[2], h0, m0); uh.z = __half_as_ushort(h0); um.z = __half_as_ushort(m0);
    split2(o[3], h0, m0); uh.w = __half_as_ushort(h0); um.w = __half_as_ushort(m0);
    ((ushort4*)(H  + (size_t)row * DDIM))[t] = uh;
    ((ushort4*)(Mp + (size_t)row * DDIM))[t] = um;
}

// ---------------- activation split (ctx only) ----------------
__global__ void __launch_bounds__(256) asplit_k(const float* __restrict__ A,
    __half* __restrict__ H, __half* __restrict__ Mp, int n4)
{
    int i = blockIdx.x * 256 + threadIdx.x;
    if (i >= n4) return;
    float4 v = ((const float4*)A)[i];
    ushort4 uh, um;
    __half h0, m0;
    split2(v.x, h0, m0); uh.x = __half_as_ushort(h0); um.x = __half_as_ushort(m0);
    split2(v.y, h0, m0); uh.y = __half_as_ushort(h0); um.y = __half_as_ushort(m0);
    split2(v.z, h0, m0); uh.z = __half_as_ushort(h0); um.z = __half_as_ushort(m0);
    split2(v.w, h0, m0); uh.w = __half_as_ushort(h0); um.w = __half_as_ushort(m0);
    ((ushort4*)H)[i] = uh; ((ushort4*)Mp)[i] = um;
}

// ---------------- weight transpose+split (batched) ----------------
struct WS6 { const float* w[6]; };

__device__ __forceinline__ void wsplit_body(const float* __restrict__ W,
    __half* __restrict__ H, __half* __restrict__ Mp, int K, int N)
{
    __shared__ float tile[32][33];
    int n0 = blockIdx.x * 32, k0 = blockIdx.y * 32;
    int tx = threadIdx.x & 31, ty = threadIdx.x >> 5;
    #pragma unroll
    for (int i = 0; i < 4; i++)
        tile[ty + i*8][tx] = W[(size_t)(k0 + ty + i*8) * N + n0 + tx];
    __syncthreads();
    #pragma unroll
    for (int i = 0; i < 4; i++) {
        int nl = ty + i*8;
        float x = tile[tx][nl];
        __half h, m;
        split2(x, h, m);
        size_t o = (size_t)(n0 + nl) * K + k0 + tx;
        H[o] = h; Mp[o] = m;
    }
}

__global__ void __launch_bounds__(256) wsplit6_k(WS6 ws,
    __half* __restrict__ H, __half* __restrict__ Mp)
{
    int z = blockIdx.z;
    size_t off = (size_t)z * 1048576;
    wsplit_body(ws.w[z], H + off, Mp + off, DDIM, DDIM);
}

__global__ void __launch_bounds__(256) wsplit_ctx2_k(const float* __restrict__ wk,
    const float* __restrict__ wv, __half* __restrict__ H, __half* __restrict__ Mp)
{
    int z = blockIdx.z;
    const float* W = z ? wv : wk;
    size_t off = OFF_WK2 + (size_t)z * 786432;
    wsplit_body(W, H + off, Mp + off, CTXD, DDIM);
}

__global__ void __launch_bounds__(256) wsplit1_k(const float* __restrict__ W,
    __half* __restrict__ H, __half* __restrict__ Mp, int K, int N)
{
    wsplit_body(W, H, Mp, K, N);
}

// ---------------- HMMA GEMM: D[M,N] = A[M,K] @ T[N,K]^T, fp16 split --------
// BK=32 (R9-proven config), 4-stage cp.async, one barrier/iter, dual
// accumulators (tile acc flushed to fp32 master every 2 iters, RN adds).
// TERMS=3: (h,m'), (m',h) [x2048] -> rescale -> (h,h)  (quantizer outputs)
// TERMS=2: (m',h) [x2048] -> rescale -> (h,h)          (smooth outputs)
// MODE 0: fake-quant -> int8, buf = head>>4 demux, per-CTA scale from table
// MODE 1: +bias+res fp32 ; MODE 2: +bias fp32
#define BM 128
#define BN 128
#define BK 32
#define ROWB 80
#define ATILE (BM*ROWB)           // 10240
#define STAGEB (2*ATILE)          // 20480
#define NSTAGE 4
#define GSMEM (NSTAGE*STAGEB)     // 81920

template<int MODE, bool BOUNDS, int TERMS>
__global__ void __launch_bounds__(256, 1) hgemm(
    const __half* __restrict__ Ah, const __half* __restrict__ Am,
    const __half* __restrict__ Bh, const __half* __restrict__ Bm,
    const float* __restrict__ bias, const float* __restrict__ res,
    float* __restrict__ Cf, char* __restrict__ Cq,
    int M, int N, int K,
    const float* __restrict__ d0, const float* __restrict__ d1,
    const float* __restrict__ d2, int rows_per_b)
{
    extern __shared__ char smem[];
    const uint32_t sb = smem_u32(smem);
    const int tid  = threadIdx.x;
    const int wid  = tid >> 5;
    const int lane = tid & 31;
    const int m0 = blockIdx.y * BM;
    const int n0 = blockIdx.x * BN;
    const int wrow = (wid >> 2) * 64;
    const int wcol = (wid & 3) * 32;

    const int KT32 = K >> 5;
    const int T = TERMS * KT32;

    const __half* APL[3];
    const __half* BPL[3];
    if (TERMS == 3) {
        APL[0]=Ah; BPL[0]=Bm;
        APL[1]=Am; BPL[1]=Bh;
        APL[2]=Ah; BPL[2]=Bh;
    } else {
        APL[0]=Am; BPL[0]=Bh;
        APL[1]=Ah; BPL[1]=Bh;
        APL[2]=Ah; BPL[2]=Bh;
    }

    int lkt = 0, lterm = 0;
    const __half* lpa = APL[0];
    const __half* lpb = BPL[0];

    const int arow = tid >> 1;
    const int aco  = (tid & 1) * 32;
    int grow = m0 + arow;
    if (BOUNDS && grow >= M) grow = M - 1;
    const int asz = (!BOUNDS || (m0 + arow) < M) ? 16 : 0;

    auto issue = [&](int buf) {
        const char* ga = (const char*)lpa + (((size_t)grow*K + lkt*BK) << 1) + aco;
        uint32_t sa = sb + buf*STAGEB + arow*ROWB + aco;
        cpasync16(sa,      ga,      asz);
        cpasync16(sa + 16, ga + 16, asz);
        const char* gb = (const char*)lpb + (((size_t)(n0+arow)*K + lkt*BK) << 1) + aco;
        uint32_t sbb = sb + buf*STAGEB + ATILE + arow*ROWB + aco;
        cpasync16(sbb,      gb,      16);
        cpasync16(sbb + 16, gb + 16, 16);
    };
    auto adv = [&]() {
        if (++lkt == KT32) {
            lkt = 0;
            ++lterm;
            int tt = lterm < TERMS ? lterm : TERMS-1;
            lpa = APL[tt];
            lpb = BPL[tt];
        }
    };

    float acc[4][4][4];
    float accm[4][4][4];
    #pragma unroll
    for (int i = 0; i < 4; i++)
        #pragma unroll
        for (int j = 0; j < 4; j++)
            #pragma unroll
            for (int r = 0; r < 4; r++) { acc[i][j][r] = 0.f; accm[i][j][r] = 0.f; }

    issue(0); adv(); cpcommit();
    issue(1); adv(); cpcommit();

    const int rescIt = (TERMS == 3) ? 2*KT32 : KT32;

    for (int it = 0; it < T; it++) {
        if (it + 2 < T) { issue((it + 2) % NSTAGE); adv(); }
        cpcommit();
        cpwait2();
        __syncthreads();
        if (it == rescIt) {
            #pragma unroll
            for (int i = 0; i < 4; i++)
                #pragma unroll
                for (int j = 0; j < 4; j++)
                    #pragma unroll
                    for (int r = 0; r < 4; r++) accm[i][j][r] *= RSCINV;
        }
        const uint32_t abase = sb + (it % NSTAGE) * STAGEB;
        const uint32_t bbase = abase + ATILE;
        #pragma unroll
        for (int kh = 0; kh < 2; kh++) {
            uint32_t b0[4], b1[4];
            #pragma unroll
            for (int nt = 0; nt < 4; nt++) {
                uint32_t ad = bbase + (wcol + nt*8 + (lane & 7))*ROWB
                            + kh*32 + ((lane >> 3) & 1)*16;
                asm volatile("ldmatrix.sync.aligned.m8n8.x2.shared.b16 {%0,%1}, [%2];"
                             : "=r"(b0[nt]), "=r"(b1[nt]) : "r"(ad));
            }
            #pragma unroll
            for (int mt = 0; mt < 4; mt++) {
                uint32_t a0, a1, a2, a3;
                uint32_t ad = abase + (wrow + mt*16 + ((lane >> 3) & 1)*8 + (lane & 7))*ROWB
                            + kh*32 + ((lane >> 4) & 1)*16;
                asm volatile("ldmatrix.sync.aligned.m8n8.x4.shared.b16 {%0,%1,%2,%3}, [%4];"
                             : "=r"(a0), "=r"(a1), "=r"(a2), "=r"(a3) : "r"(ad));
                #pragma unroll
                for (int nt = 0; nt < 4; nt++) {
                    asm volatile(
                        "mma.sync.aligned.m16n8k16.row.col.f32.f16.f16.f32 "
                        "{%0,%1,%2,%3}, {%4,%5,%6,%7}, {%8,%9}, {%0,%1,%2,%3};"
                        : "+f"(acc[mt][nt][0]), "+f"(acc[mt][nt][1]),
                          "+f"(acc[mt][nt][2]), "+f"(acc[mt][nt][3])
                        : "r"(a0), "r"(a1), "r"(a2), "r"(a3), "r"(b0[nt]), "r"(b1[nt]));
                }
            }
        }
        if (it & 1) {
            #pragma unroll
            for (int i = 0; i < 4; i++)
                #pragma unroll
                for (int j = 0; j < 4; j++)
                    #pragma unroll
                    for (int r = 0; r < 4; r++) {
                        accm[i][j][r] += acc[i][j][r];
                        acc[i][j][r] = 0.f;
                    }
        }
    }

    // ---------------- epilogue ----------------
    float d = 0.f, invd = 0.f;
    if (MODE == 0) {
        int bsel = n0 >> 10;   // per-CTA constant (tile never crosses a 1024 boundary)
        const float* dp = (bsel == 0) ? d0 : ((bsel == 1) ? d1 : d2);
        d = *dp; invd = 1.0f / d;
    }
    #pragma unroll
    for (int mt = 0; mt < 4; mt++) {
        int r0 = m0 + wrow + mt*16 + (lane >> 2);
        #pragma unroll
        for (int nt = 0; nt < 4; nt++) {
            int nc = n0 + wcol + nt*8 + (lane & 3)*2;
            #pragma unroll
            for (int hrow = 0; hrow < 2; hrow++) {
                int rr = r0 + hrow*8;
                if (BOUNDS && rr >= M) continue;
                float c0 = accm[mt][nt][hrow*2+0];
                float c1 = accm[mt][nt][hrow*2+1];
                if (MODE == 0) {
                    int hg = nc >> 6;
                    int buf = hg >> 4;
                    int hl  = hg & 15;
                    int dd  = nc & 63;
                    int b = rr / rows_per_b;
                    int n = rr - b * rows_per_b;
                    char2 pk;
                    pk.x = (char)(int)fminf(fmaxf(rintf(c0 * invd), -128.f), 127.f);
                    pk.y = (char)(int)fminf(fmaxf(rintf(c1 * invd), -128.f), 127.f);
                    *(char2*)(Cq + (size_t)buf*QKVSTRIDE
                              + ((size_t)(b*HH + hl)*rows_per_b + n)*64 + dd) = pk;
                } else {
                    size_t off = (size_t)rr * N + nc;
                    float2 o;
                    o.x = c0 + bias[nc];
                    o.y = c1 + bias[nc+1];
                    if (MODE == 1) {
                        float2 rv = *(const float2*)(res + off);
                        o.x += rv.x; o.y += rv.y;
                    }
                    *(float2*)(Cf + off) = o;
                }
            }
        }
    }
}

// ---------------- int8 scores ----------------
__global__ void __launch_bounds__(256) sim8_kernel(
    const char* __restrict__ Q8, const char* __restrict__ K8,
    float* __restrict__ S, int nk,
    const float* __restrict__ dq, const float* __restrict__ dk)
{
    int bh = blockIdx.z;
    int i0 = blockIdx.y * 64;
    int j0 = blockIdx.x * 64;
    __shared__ int qs[16][68];
    __shared__ int ks[16][68];
    int tid = threadIdx.x;
    int row = tid >> 2;
    int c4  = (tid & 3) * 4;
    {
        int4 qv = *(const int4*)(Q8 + ((size_t)bh*NN + i0 + row)*64 + c4*4);
        qs[c4+0][row]=qv.x; qs[c4+1][row]=qv.y; qs[c4+2][row]=qv.z; qs[c4+3][row]=qv.w;
        int jr = j0 + row;
        int4 kv = make_int4(0,0,0,0);
        if (jr < nk) kv = *(const int4*)(K8 + ((size_t)bh*nk + jr)*64 + c4*4);
        ks[c4+0][row]=kv.x; ks[c4+1][row]=kv.y; ks[c4+2][row]=kv.z; ks[c4+3][row]=kv.w;
    }
    __syncthreads();
    int ty = tid >> 4, tx = tid & 15;
    int acc[4][4];
    #pragma unroll
    for (int i = 0; i < 4; i++)
        #pragma unroll
        for (int j = 0; j < 4; j++) acc[i][j] = 0;
    #pragma unroll
    for (int kk = 0; kk < 16; kk++) {
        int a[4], b[4];
        *(int4*)a = *(const int4*)&qs[kk][ty*4];
        *(int4*)b = *(const int4*)&ks[kk][tx*4];
        #pragma unroll
        for (int i = 0; i < 4; i++)
            #pragma unroll
            for (int j = 0; j < 4; j++) acc[i][j] = __dp4a(a[i], b[j], acc[i][j]);
    }
    float sc = dq[0] * dk[0] * SCALE;
    #pragma unroll
    for (int i = 0; i < 4; i++) {
        size_t ro = ((size_t)bh*NN + i0 + ty*4 + i) * nk;
        #pragma unroll
        for (int j = 0; j < 4; j++) {
            int jj = j0 + tx*4 + j;
            if (jj < nk) S[ro + jj] = (float)acc[i][j] * sc;
        }
    }
}

// ---------------- softmax + weight quant ----------------
__global__ void __launch_bounds__(128) softmax_quant(
    const float* __restrict__ S, unsigned char* __restrict__ W8,
    int cols, int colsp, const float* __restrict__ dptr)
{
    size_t row = blockIdx.x;
    const float* p = S + row * (size_t)cols;
    unsigned char* o = W8 + row * (size_t)colsp;
    int t = threadIdx.x;
    float buf[8];
    int nb = 0;
    float m = -INFINITY;
    for (int c = t; c < cols; c += 128) {
        float v = p[c];
        buf[nb++] = v;
        m = fmaxf(m, v);
    }
    #pragma unroll
    for (int off = 16; off; off >>= 1) m = fmaxf(m, __shfl_xor_sync(0xffffffffu, m, off));
    __shared__ float redm[4], reds[4];
    if ((t & 31) == 0) redm[t >> 5] = m;
    __syncthreads();
    m = fmaxf(fmaxf(redm[0], redm[1]), fmaxf(redm[2], redm[3]));
    float sum = 0.f;
    for (int i = 0; i < nb; i++) { buf[i] = expf(buf[i] - m); sum += buf[i]; }
    #pragma unroll
    for (int off = 16; off; off >>= 1) sum += __shfl_xor_sync(0xffffffffu, sum, off);
    if ((t & 31) == 0) reds[t >> 5] = sum;
    __syncthreads();
    sum = reds[0] + reds[1] + reds[2] + reds[3];
    float inv = 1.0f / sum;
    float invd = 1.0f / dptr[0];
    nb = 0;
    for (int c = t; c < colsp; c += 128) {
        unsigned char ob = 0;
        if (c < cols) {
            float q = rintf(buf[nb++] * inv * invd);
            ob = (unsigned char)(int)fminf(fmaxf(q, 0.f), 255.f);
        }
        o[c] = ob;
    }
}

// ---------------- AV (u8 x s8 dp4a) -> (h,m) planes ----------------
__global__ void __launch_bounds__(256) av8_kernel(
    const unsigned char* __restrict__ W8, const char* __restrict__ V8,
    __half* __restrict__ OH, __half* __restrict__ OM, int nk, int colsp,
    const float* __restrict__ dw, const float* __restrict__ dv)
{
    int bh = blockIdx.y; int b = bh >> 4; int h = bh & 15;
    int i0 = blockIdx.x * 64;
    __shared__ int ws[64][20];
    __shared__ unsigned char vtb[64][76];
    int tid = threadIdx.x;
    int row = tid >> 2;
    int c16 = (tid & 3) * 16;
    int ty = tid >> 4, tx = tid & 15;
    int acc[4][4];
    #pragma unroll
    for (int i = 0; i < 4; i++)
        #pragma unroll
        for (int d = 0; d < 4; d++) acc[i][d] = 0;

    const unsigned char* wb = W8 + ((size_t)bh*NN + i0 + row) * colsp + c16;
    const char* vb = V8 + ((size_t)bh*nk)*64;

    for (int j0 = 0; j0 < nk; j0 += 64) {
        uint4 wv = *(const uint4*)(wb + j0);
        *(uint4*)&ws[row][(tid & 3) * 4] = wv;
        int jr = j0 + row;
        int4 vv = make_int4(0,0,0,0);
        if (jr < nk) vv = *(const int4*)(vb + (size_t)jr*64 + c16);
        union { int4 v; unsigned char bb[16]; } u; u.v = vv;
        #pragma unroll
        for (int i = 0; i < 16; i++) vtb[c16 + i][row] = u.bb[i];
        __syncthreads();
        #pragma unroll
        for (int kk = 0; kk < 16; kk++) {
            int a[4], bb[4];
            #pragma unroll
            for (int i = 0; i < 4; i++) a[i] = ws[ty*4 + i][kk];
            #pragma unroll
            for (int d = 0; d < 4; d++) bb[d] = *(const int*)&vtb[tx*4 + d][kk*4];
            #pragma unroll
            for (int i = 0; i < 4; i++)
                #pragma unroll
                for (int d = 0; d < 4; d++)
                    asm("dp4a.u32.s32 %0, %1, %2, %3;"
                        : "=r"(acc[i][d]) : "r"(a[i]), "r"(bb[d]), "r"(acc[i][d]));
        }
        __syncthreads();
    }
    float sc = dw[0] * dv[0];
    #pragma unroll
    for (int i = 0; i < 4; i++) {
        size_t ro = ((size_t)(b*NN + i0 + ty*4 + i)) * DDIM + h*64 + tx*4;
        ushort4 uh, um;
        __half hh, mm;
        split2((float)acc[i][0] * sc, hh, mm); uh.x=__half_as_ushort(hh); um.x=__half_as_ushort(mm);
        split2((float)acc[i][1] * sc, hh, mm); uh.y=__half_as_ushort(hh); um.y=__half_as_ushort(mm);
        split2((float)acc[i][2] * sc, hh, mm); uh.z=__half_as_ushort(hh); um.z=__half_as_ushort(mm);
        split2((float)acc[i][3] * sc, hh, mm); uh.w=__half_as_ushort(hh); um.w=__half_as_ushort(mm);
        *(ushort4*)&OH[ro] = uh;
        *(ushort4*)&OM[ro] = um;
    }
}

// ---------------- GEGLU -> (h,m) planes ----------------
__global__ void __launch_bounds__(256) geglu_kernel(const float* __restrict__ h,
    __half* __restrict__ AH, __half* __restrict__ AM)
{
    size_t idx = (size_t)blockIdx.x * blockDim.x + threadIdx.x;
    size_t i  = idx / (FFHID / 4);
    size_t c4 = idx % (FFHID / 4);
    float4 a = *(const float4*)(h + i * FFIN + c4 * 4);
    float4 g = *(const float4*)(h + i * FFIN + FFHID + c4 * 4);
    const float kInvSqrt2 = 0.70710678118654752f;
    float o[4];
    o[0] = a.x * (0.5f * g.x * (1.f + erff(g.x * kInvSqrt2)));
    o[1] = a.y * (0.5f * g.y * (1.f + erff(g.y * kInvSqrt2)));
    o[2] = a.z * (0.5f * g.z * (1.f + erff(g.z * kInvSqrt2)));
    o[3] = a.w * (0.5f * g.w * (1.f + erff(g.w * kInvSqrt2)));
    ushort4 uh, um;
    __half hh, mm;
    split2(o[0], hh, mm); uh.x=__half_as_ushort(hh); um.x=__half_as_ushort(mm);
    split2(o[1], hh, mm); uh.y=__half_as_ushort(hh); um.y=__half_as_ushort(mm);
    split2(o[2], hh, mm); uh.z=__half_as_ushort(hh); um.z=__half_as_ushort(mm);
    split2(o[3], hh, mm); uh.w=__half_as_ushort(hh); um.w=__half_as_ushort(mm);
    ((ushort4*)AH)[idx] = uh;
    ((ushort4*)AM)[idx] = um;
}

// ---------------- launch ----------------
extern "C" void kernel_launch(void* const* d_in, const int* in_sizes, int n_in,
                              void* d_out, int out_size)
{
    const float* x    = (const float*)d_in[0];
    const float* ctx  = (const float*)d_in[1];
    const float* n1w  = (const float*)d_in[2];
    const float* n1b  = (const float*)d_in[3];
    const float* n2w  = (const float*)d_in[4];
    const float* n2b  = (const float*)d_in[5];
    const float* n3w  = (const float*)d_in[6];
    const float* n3b  = (const float*)d_in[7];
    const float* a1wq = (const float*)d_in[8];
    const float* a1wk = (const float*)d_in[9];
    const float* a1wv = (const float*)d_in[10];
    const float* a1wo = (const float*)d_in[11];
    const float* a1bo = (const float*)d_in[12];
    const float* a2wq = (const float*)d_in[13];
    const float* a2wk = (const float*)d_in[14];
    const float* a2wv = (const float*)d_in[15];
    const float* a2wo = (const float*)d_in[16];
    const float* a2bo = (const float*)d_in[17];
    const float* ffw1 = (const float*)d_in[18];
    const float* ffb1 = (const float*)d_in[19];
    const float* ffw2 = (const float*)d_in[20];
    const float* ffb2 = (const float*)d_in[21];
    const float* d1q  = (const float*)d_in[22];
    const float* d1k  = (const float*)d_in[23];
    const float* d1v  = (const float*)d_in[24];
    const float* d1w  = (const float*)d_in[25];
    const float* d2q  = (const float*)d_in[26];
    const float* d2k  = (const float*)d_in[27];
    const float* d2v  = (const float*)d_in[28];
    const float* d2w  = (const float*)d_in[29];
    float* out = (float*)d_out;

    float *sim;
    char *qkv8;
    unsigned char *w8;
    __half *ah, *am, *wh, *wm;
    cudaGetSymbolAddress((void**)&sim,  g_sim);
    cudaGetSymbolAddress((void**)&qkv8, g_qkv8);
    cudaGetSymbolAddress((void**)&w8,   g_w8);
    cudaGetSymbolAddress((void**)&ah,   g_ah);
    cudaGetSymbolAddress((void**)&am,   g_am);
    cudaGetSymbolAddress((void**)&wh,   g_wh);
    cudaGetSymbolAddress((void**)&wm,   g_wm);
    char* q8 = qkv8;
    char* k8 = qkv8 + QKVSTRIDE;
    char* v8 = qkv8 + 2*QKVSTRIDE;
    float* hbuf = sim;

    cudaFuncSetAttribute(hgemm<0,false,3>, cudaFuncAttributeMaxDynamicSharedMemorySize, GSMEM);
    cudaFuncSetAttribute(hgemm<0,true ,3>, cudaFuncAttributeMaxDynamicSharedMemorySize, GSMEM);
    cudaFuncSetAttribute(hgemm<1,false,3>, cudaFuncAttributeMaxDynamicSharedMemorySize, GSMEM);
    cudaFuncSetAttribute(hgemm<1,false,2>, cudaFuncAttributeMaxDynamicSharedMemorySize, GSMEM);
    cudaFuncSetAttribute(hgemm<2,false,2>, cudaFuncAttributeMaxDynamicSharedMemorySize, GSMEM);

    // ---- split all weights (batched; 4 launches) ----
    WS6 ws6;
    ws6.w[0] = a1wq; ws6.w[1] = a1wk; ws6.w[2] = a1wv;
    ws6.w[3] = a1wo; ws6.w[4] = a2wq; ws6.w[5] = a2wo;
    wsplit6_k<<<dim3(DDIM/32, DDIM/32, 6), 256>>>(ws6, wh, wm);
    wsplit_ctx2_k<<<dim3(DDIM/32, CTXD/32, 2), 256>>>(a2wk, a2wv, wh, wm);
    wsplit1_k<<<dim3(FFIN/32, DDIM/32), 256>>>(ffw1, wh+OFF_FF1, wm+OFF_FF1, DDIM, FFIN);
    wsplit1_k<<<dim3(DDIM/32, FFHID/32), 256>>>(ffw2, wh+OFF_FF2, wm+OFF_FF2, FFHID, DDIM);

    // ---- attn1 (self): FUSED qkv GEMM (N=3072, per-buf scales) ----
    ln_kernel<<<TOK, 256>>>(x, n1w, n1b, ah, am);
    hgemm<0,false,3><<<dim3(24,32), 256, GSMEM>>>(ah,am, wh+OFF_WQ1,wm+OFF_WQ1,
        nullptr, nullptr, nullptr, qkv8, TOK, 3072, DDIM, d1q, d1k, d1v, NN);
    sim8_kernel<<<dim3(16,16,BB*HH), 256>>>(q8, k8, sim, NN, d1q, d1k);
    softmax_quant<<<BB*HH*NN, 128>>>(sim, w8, NN, NN, d1w);
    av8_kernel<<<dim3(16,BB*HH), 256>>>(w8, v8, ah, am, NN, NN, d1w, d1v);
    hgemm<1,false,3><<<dim3(8,32), 256, GSMEM>>>(ah,am, wh+OFF_WO1,wm+OFF_WO1,
        a1bo, x, out, nullptr, TOK, DDIM, DDIM, nullptr, nullptr, nullptr, 0);

    // ---- attn2 (cross): q2 alone; k2+v2 FUSED (N=2048) ----
    ln_kernel<<<TOK, 256>>>(out, n2w, n2b, ah, am);
    hgemm<0,false,3><<<dim3(8,32), 256, GSMEM>>>(ah,am, wh+OFF_WQ2,wm+OFF_WQ2,
        nullptr, nullptr, nullptr, q8, TOK, DDIM, DDIM, d2q, d2q, d2q, NN);
    asplit_k<<<(CTOK*CTXD/4 + 255)/256, 256>>>(ctx, ah, am, CTOK*CTXD/4);
    hgemm<0,true ,3><<<dim3(16,3), 256, GSMEM>>>(ah,am, wh+OFF_WK2,wm+OFF_WK2,
        nullptr, nullptr, nullptr, k8, CTOK, 2048, CTXD, d2k, d2v, d2v, CTXN);
    sim8_kernel<<<dim3(2,16,BB*HH), 256>>>(q8, k8, sim, CTXN, d2q, d2k);
    softmax_quant<<<BB*HH*NN, 128>>>(sim, w8, CTXN, 128, d2w);
    av8_kernel<<<dim3(16,BB*HH), 256>>>(w8, v8, ah, am, CTXN, 128, d2w, d2v);
    hgemm<1,false,2><<<dim3(8,32), 256, GSMEM>>>(ah,am, wh+OFF_WO2,wm+OFF_WO2,
        a2bo, out, out, nullptr, TOK, DDIM, DDIM, nullptr, nullptr, nullptr, 0);

    // ---- GEGLU FF ----
    ln_kernel<<<TOK, 256>>>(out, n3w, n3b, ah, am);
    hgemm<2,false,2><<<dim3(64,32), 256, GSMEM>>>(ah,am, wh+OFF_FF1,wm+OFF_FF1,
        ffb1, nullptr, hbuf, nullptr, TOK, FFIN, DDIM, nullptr, nullptr, nullptr, 0);
    geglu_kernel<<<(TOK*(FFHID/4))/256, 256>>>(hbuf, ah, am);
    hgemm<1,false,2><<<dim3(8,32), 256, GSMEM>>>(ah,am, wh+OFF_FF2,wm+OFF_FF2,
        ffb2, out, out, nullptr, TOK, DDIM, FFHID, nullptr, nullptr, nullptr, 0);
}